// round 13
// baseline (speedup 1.0000x reference)
#include <cuda_runtime.h>
#include <cuda_bf16.h>
#include <math.h>

#define C_PROTO 100000
#define D_DIM   256
#define P_PAIRS 65536
#define K_NEG   4
#define BETA    0.1f
#define MARGIN  0.1f
#define EPS     1e-6f
#define PI_F    3.14159265358979f
#define PIO2_F  1.57079632679490f

#define NBLOCKS 2048
#define NTHREADS 256
#define NWARPS_TOTAL ((NBLOCKS * NTHREADS) / 32)

#define NORM_BLOCKS ((C_PROTO + 7) / 8)   // 8 rows (warps) per 256-thread block

// scratch (no runtime allocation allowed)
__device__ float          g_norm2[C_PROTO];             // |proto[i]|^2 (fp32, exact-ish)
__device__ __nv_bfloat16  g_bf16[(size_t)C_PROTO * D_DIM]; // 51.2 MB bf16 copy (L2-resident)
__device__ float2         g_partials[NBLOCKS];
__device__ unsigned int   g_count;                      // zero-init; last block resets

__device__ __forceinline__ float fsqrt_approx(float x) {
    float r;
    asm("sqrt.approx.f32 %0, %1;" : "=f"(r) : "f"(x));
    return r;
}

// Abramowitz-Stegun 4.4.45: max abs err 6.7e-5 rad
__device__ __forceinline__ float acos_approx(float x) {
    const float ax = fabsf(x);
    float p = fmaf(-0.0187293f, ax, 0.0742610f);
    p = fmaf(p, ax, -0.2121144f);
    p = fmaf(p, ax, 1.5707288f);
    const float s = fsqrt_approx(1.0f - ax) * p;
    return (x >= 0.0f) ? s : (PI_F - s);
}

// asin(y), y in [0, 1)
__device__ __forceinline__ float asin_approx_pos(float y) {
    float p = fmaf(-0.0187293f, y, 0.0742610f);
    p = fmaf(p, y, -0.2121144f);
    p = fmaf(p, y, 1.5707288f);
    return PIO2_F - fsqrt_approx(1.0f - y) * p;
}

__device__ __forceinline__ float dot4(float4 a, float4 b) {
    return a.x * b.x + a.y * b.y + a.z * b.z + a.w * b.w;
}

__device__ __forceinline__ float warp_sum(float v) {
#pragma unroll
    for (int o = 16; o > 0; o >>= 1)
        v += __shfl_xor_sync(0xffffffffu, v, o);
    return v;
}

// Reduce 4 independent values via octant packing (~24 instr vs 80).
__device__ __forceinline__ void warp_sum4(float v0, float v1, float v2, float v3,
                                          bool lo16, bool lo8,
                                          float& r0, float& r1, float& r2, float& r3)
{
    const unsigned m = 0xffffffffu;
    float s01 = (lo16 ? v0 : v1) + __shfl_xor_sync(m, lo16 ? v1 : v0, 16);
    float s23 = (lo16 ? v2 : v3) + __shfl_xor_sync(m, lo16 ? v3 : v2, 16);
    float t   = (lo8 ? s01 : s23) + __shfl_xor_sync(m, lo8 ? s23 : s01, 8);
    t += __shfl_xor_sync(m, t, 4);
    t += __shfl_xor_sync(m, t, 2);
    t += __shfl_xor_sync(m, t, 1);
    r0 = __shfl_sync(m, t, 0);
    r2 = __shfl_sync(m, t, 8);
    r1 = __shfl_sync(m, t, 16);
    r3 = __shfl_sync(m, t, 24);
}

__device__ __forceinline__ unsigned pack_bf16x2(float a, float b) {
    __nv_bfloat162 h = __floats2bfloat162_rn(a, b);
    return *reinterpret_cast<unsigned*>(&h);
}

// ---------- pass 1: norms + bf16 table (one warp per row) ----------
__global__ void __launch_bounds__(256)
norm_convert_kernel(const float* __restrict__ proto)
{
    const int lane = threadIdx.x & 31;
    const int row  = blockIdx.x * 8 + (threadIdx.x >> 5);
    if (row >= C_PROTO) return;
    const float4* rb = (const float4*)(proto + (size_t)row * D_DIM);
    const float4 a = rb[lane];         // elements 4l .. 4l+3
    const float4 b = rb[lane + 32];    // elements 128+4l .. 128+4l+3

    float s = dot4(a, a) + dot4(b, b);
    s = warp_sum(s);
    if (lane == 0) g_norm2[row] = s;

    // write bf16 copy (element order preserved)
    uint2* dst = (uint2*)(g_bf16 + (size_t)row * D_DIM);
    uint2 ua, ub;
    ua.x = pack_bf16x2(a.x, a.y);  ua.y = pack_bf16x2(a.z, a.w);
    ub.x = pack_bf16x2(b.x, b.y);  ub.y = pack_bf16x2(b.z, b.w);
    dst[lane]      = ua;
    dst[lane + 32] = ub;
}

// ---------- pass 2: energy (bf16 gathers) + fused final reduction ----------
__global__ void __launch_bounds__(NTHREADS, 4)
energy_kernel(const int*   __restrict__ pairs,
              const int*   __restrict__ negc,
              float*       __restrict__ out)
{
    const int lane    = threadIdx.x & 31;
    const int warp_id = (blockIdx.x * NTHREADS + threadIdx.x) >> 5;
    const bool lo16 = (lane < 16);
    const bool lo8  = ((lane & 8) == 0);

    float pos_sum = 0.0f;
    float neg_sum = 0.0f;

    for (int i = warp_id; i < P_PAIRS; i += NWARPS_TOTAL) {
        const int2 pr = *(const int2*)(pairs + 2 * i);
        const int4 ng = *(const int4*)(negc + 4 * i);
        int cidx[5];
        cidx[0] = pr.y;
        cidx[1] = ng.x; cidx[2] = ng.y; cidx[3] = ng.z; cidx[4] = ng.w;

        // ---- one 16B load per vector: lane holds elements 8l..8l+7 ----
        const uint4 praw = ((const uint4*)(g_bf16 + (size_t)pr.x * D_DIM))[lane];
        uint4 craw[5];
#pragma unroll
        for (int k = 0; k < 5; k++)
            craw[k] = ((const uint4*)(g_bf16 + (size_t)cidx[k] * D_DIM))[lane];

        // norm lookups (warp-uniform broadcast; fly with the gathers)
        const float ppn = g_norm2[pr.x];
        float ccn[5];
#pragma unroll
        for (int k = 0; k < 5; k++) ccn[k] = g_norm2[cidx[k]];

        // parent -> fp32 once
        float2 pf[4];
        {
            const __nv_bfloat162* ph = (const __nv_bfloat162*)&praw;
#pragma unroll
            for (int w = 0; w < 4; w++) pf[w] = __bfloat1622float2(ph[w]);
        }

        // ---- c.p dot products ----
        float cp[5];
#pragma unroll
        for (int k = 0; k < 5; k++) {
            const __nv_bfloat162* ch = (const __nv_bfloat162*)&craw[k];
            float acc = 0.0f;
#pragma unroll
            for (int w = 0; w < 4; w++) {
                float2 cf = __bfloat1622float2(ch[w]);
                acc = fmaf(cf.x, pf[w].x, acc);
                acc = fmaf(cf.y, pf[w].y, acc);
            }
            cp[k] = acc;
        }

        // reductions: one plain butterfly + one packed 4-way
        cp[0] = warp_sum(cp[0]);
        warp_sum4(cp[1], cp[2], cp[3], cp[4], lo16, lo8,
                  cp[1], cp[2], cp[3], cp[4]);

        // ---- scalar epilogue (warp-uniform) ----
        const float norm_p = fsqrt_approx(ppn);
        const float ap_arg = fminf(__fdividef(BETA, norm_p + EPS), 1.0f - EPS);
        const float aperture = asin_approx_pos(ap_arg);
        const float denom_base = 2.0f * norm_p;

#pragma unroll
        for (int k = 0; k < 5; k++) {
            const float dd  = fmaxf(fmaf(-2.0f, cp[k], ccn[k] + ppn), 0.0f);
            const float num = 2.0f * (cp[k] - ppn);
            const float denom = fmaf(denom_base, fsqrt_approx(dd), EPS);
            float cosang = __fdividef(num, denom);
            cosang = fminf(fmaxf(cosang, -1.0f + EPS), 1.0f - EPS);
            // self-pair (c==p): reference gets num==0 exactly -> cosang 0.
            cosang = (dd >= 1.0f) ? cosang : 0.0f;
            const float ang = acos_approx(cosang);
            const float e   = fmaxf(ang - aperture, 0.0f);
            if (k == 0) pos_sum += e;
            else        neg_sum += fmaxf(MARGIN - e, 0.0f);
        }
    }

    // per-block reduction (pos/neg are warp-uniform)
    __shared__ float2 s[NTHREADS / 32];
    __shared__ bool   s_last;
    if (lane == 0)
        s[threadIdx.x >> 5] = make_float2(pos_sum, neg_sum);
    __syncthreads();
    if (threadIdx.x == 0) {
        float2 acc = s[0];
#pragma unroll
        for (int w = 1; w < NTHREADS / 32; w++) {
            acc.x += s[w].x;
            acc.y += s[w].y;
        }
        g_partials[blockIdx.x] = acc;
        __threadfence();
        unsigned int t = atomicAdd(&g_count, 1u);
        s_last = (t == (unsigned int)(NBLOCKS - 1));
    }
    __syncthreads();

    if (s_last) {
        __shared__ float sx[NTHREADS];
        __shared__ float sy[NTHREADS];
        float ax = 0.0f, ay = 0.0f;
        for (int b = threadIdx.x; b < NBLOCKS; b += NTHREADS) {
            float2 v = g_partials[b];
            ax += v.x;
            ay += v.y;
        }
        sx[threadIdx.x] = ax;
        sy[threadIdx.x] = ay;
        __syncthreads();
#pragma unroll
        for (int st = NTHREADS / 2; st > 0; st >>= 1) {
            if (threadIdx.x < st) {
                sx[threadIdx.x] += sx[threadIdx.x + st];
                sy[threadIdx.x] += sy[threadIdx.x + st];
            }
            __syncthreads();
        }
        if (threadIdx.x == 0) {
            const float avg_pos = sx[0] / (float)P_PAIRS;
            const float avg_neg = sy[0] / (float)(P_PAIRS * K_NEG);
            out[0] = (avg_pos + avg_neg) * 0.5f;
            g_count = 0;   // reset for next graph replay
        }
    }
}

extern "C" void kernel_launch(void* const* d_in, const int* in_sizes, int n_in,
                              void* d_out, int out_size)
{
    (void)in_sizes; (void)n_in; (void)out_size;
    const float* proto = (const float*)d_in[0];
    const int*   pairs = (const int*)d_in[1];
    const int*   negc  = (const int*)d_in[2];
    float* out = (float*)d_out;

    norm_convert_kernel<<<NORM_BLOCKS, 256>>>(proto);
    energy_kernel<<<NBLOCKS, NTHREADS>>>(pairs, negc, out);
}

// round 17
// speedup vs baseline: 1.2290x; 1.2290x over previous
#include <cuda_runtime.h>
#include <math.h>

#define C_PROTO 100000
#define D_DIM   256
#define P_PAIRS 65536
#define K_NEG   4
#define BETA    0.1f
#define MARGIN  0.1f
#define EPS     1e-6f
#define PI_F    3.14159265358979f
#define PIO2_F  1.57079632679490f

#define NBLOCKS 2048
#define NTHREADS 256
#define NWARPS_TOTAL ((NBLOCKS * NTHREADS) / 32)

#define QNT_BLOCKS ((C_PROTO + 7) / 8)   // 8 rows (warps) per 256-thread block

// ---- scratch (no runtime allocation allowed) ----
// int8 quantized prototype table: 25.6 MB (stays L2-resident)
__device__ unsigned int g_q8[(size_t)C_PROTO * (D_DIM / 4)];
// per-row (norm^2 fp32 exact, dequant scale): 800 KB
__device__ float2 g_info[C_PROTO];
__device__ float2 g_partials[NBLOCKS];
__device__ unsigned int g_count;         // zero-init; last block resets each launch

__device__ __forceinline__ float fsqrt_approx(float x) {
    float r;
    asm("sqrt.approx.f32 %0, %1;" : "=f"(r) : "f"(x));
    return r;
}

// Abramowitz-Stegun 4.4.45: max abs err 6.7e-5 rad
__device__ __forceinline__ float acos_approx(float x) {
    const float ax = fabsf(x);
    float p = fmaf(-0.0187293f, ax, 0.0742610f);
    p = fmaf(p, ax, -0.2121144f);
    p = fmaf(p, ax, 1.5707288f);
    const float s = fsqrt_approx(1.0f - ax) * p;
    return (x >= 0.0f) ? s : (PI_F - s);
}

// asin(y), y in [0, 1)
__device__ __forceinline__ float asin_approx_pos(float y) {
    float p = fmaf(-0.0187293f, y, 0.0742610f);
    p = fmaf(p, y, -0.2121144f);
    p = fmaf(p, y, 1.5707288f);
    return PIO2_F - fsqrt_approx(1.0f - y) * p;
}

__device__ __forceinline__ float dot4(float4 a, float4 b) {
    return a.x * b.x + a.y * b.y + a.z * b.z + a.w * b.w;
}

__device__ __forceinline__ float warp_sum_f(float v) {
#pragma unroll
    for (int o = 16; o > 0; o >>= 1)
        v += __shfl_xor_sync(0xffffffffu, v, o);
    return v;
}

__device__ __forceinline__ unsigned int quant_pack4(float4 v, float inv_s) {
    int a = __float2int_rn(v.x * inv_s);
    int b = __float2int_rn(v.y * inv_s);
    int c = __float2int_rn(v.z * inv_s);
    int d = __float2int_rn(v.w * inv_s);
    return (unsigned)(a & 0xFF) | ((unsigned)(b & 0xFF) << 8) |
           ((unsigned)(c & 0xFF) << 16) | ((unsigned)(d & 0xFF) << 24);
}

// ---------- pass 1: exact fp32 norms + int8 quantized table (one warp per row) ----------
__global__ void __launch_bounds__(256)
quant_kernel(const float* __restrict__ proto)
{
    const int lane = threadIdx.x & 31;
    const int row  = blockIdx.x * 8 + (threadIdx.x >> 5);
    if (row >= C_PROTO) return;

    const float4* rb = (const float4*)(proto + (size_t)row * D_DIM);
    const float4 a = rb[lane];         // elements 4l .. 4l+3
    const float4 b = rb[lane + 32];    // elements 128+4l .. 128+4l+3

    // exact norm^2 (fp32 tree)
    float s = dot4(a, a) + dot4(b, b);
    s = warp_sum_f(s);

    // row max-abs via integer REDUX (positive floats order as uints)
    float ma = fmaxf(fmaxf(fabsf(a.x), fabsf(a.y)), fmaxf(fabsf(a.z), fabsf(a.w)));
    ma = fmaxf(ma, fmaxf(fmaxf(fabsf(b.x), fabsf(b.y)), fmaxf(fabsf(b.z), fabsf(b.w))));
    unsigned mu = __reduce_max_sync(0xffffffffu, __float_as_uint(ma));
    const float maxabs = __uint_as_float(mu);

    const float scale  = fmaxf(maxabs, 1e-20f) * (1.0f / 127.0f);
    const float inv_s  = 127.0f / fmaxf(maxabs, 1e-20f);

    // quantize + pack: lane writes words [2l] (elems 4l..) and [64+2l] (elems 128+4l..)
    unsigned int* dst = g_q8 + (size_t)row * (D_DIM / 4);
    uint2 w0, w1;
    w0.x = quant_pack4(a, inv_s);
    // element order within the row: a covers 4l..4l+3, b covers 128+4l..128+4l+3.
    // store interleaved consistently: word index = element_index/4.
    dst[lane]      = w0.x;                 // elems 4l..4l+3  -> word l? (see below)
    // NOTE: word for elements 4l..4l+3 is index l... but we loaded float4 at index lane
    // and lane+32, i.e. elems 4*lane and 128+4*lane -> words lane and 32+lane? No:
    // word = elem/4, elems 4*lane.. -> word lane; elems 128+4*lane -> word 32+lane.
    w1.x = quant_pack4(b, inv_s);
    dst[lane + 32] = w1.x;

    if (lane == 0) g_info[row] = make_float2(s, scale);
}

// ---------- pass 2: energy (int8 dp4a gathers) + fused final reduction ----------
__global__ void __launch_bounds__(NTHREADS, 4)
energy_kernel(const int* __restrict__ pairs,
              const int* __restrict__ negc,
              float*     __restrict__ out)
{
    const int lane    = threadIdx.x & 31;
    const int warp_id = (blockIdx.x * NTHREADS + threadIdx.x) >> 5;

    float pos_sum = 0.0f;
    float neg_sum = 0.0f;

    for (int i = warp_id; i < P_PAIRS; i += NWARPS_TOTAL) {
        const int2 pr = *(const int2*)(pairs + 2 * i);
        const int4 ng = *(const int4*)(negc + 4 * i);
        int cidx[5];
        cidx[0] = pr.y;
        cidx[1] = ng.x; cidx[2] = ng.y; cidx[3] = ng.z; cidx[4] = ng.w;

        // one 8B load per vector: lane holds elements 8l..8l+7 (words 2l, 2l+1)
        const uint2 praw = ((const uint2*)(g_q8 + (size_t)pr.x * (D_DIM / 4)))[lane];
        uint2 craw[5];
#pragma unroll
        for (int k = 0; k < 5; k++)
            craw[k] = ((const uint2*)(g_q8 + (size_t)cidx[k] * (D_DIM / 4)))[lane];

        // per-row info (warp-uniform broadcast loads, fly with gathers)
        const float2 ip = g_info[pr.x];
        float2 ic[5];
#pragma unroll
        for (int k = 0; k < 5; k++) ic[k] = g_info[cidx[k]];

        // integer dot products: 2 dp4a per child
        int cpi[5];
#pragma unroll
        for (int k = 0; k < 5; k++) {
            int acc = __dp4a((int)craw[k].x, (int)praw.x, 0);
            cpi[k]  = __dp4a((int)craw[k].y, (int)praw.y, acc);
        }

        // 5 single-instruction integer warp reductions (REDUX.SUM)
#pragma unroll
        for (int k = 0; k < 5; k++)
            cpi[k] = __reduce_add_sync(0xffffffffu, cpi[k]);

        // ---- scalar epilogue (warp-uniform) ----
        const float ppn = ip.x;
        const float norm_p = fsqrt_approx(ppn);
        const float ap_arg = fminf(__fdividef(BETA, norm_p + EPS), 1.0f - EPS);
        const float aperture = asin_approx_pos(ap_arg);
        const float denom_base = 2.0f * norm_p;

#pragma unroll
        for (int k = 0; k < 5; k++) {
            const float cp  = __int2float_rn(cpi[k]) * (ip.y * ic[k].y);
            const float dd  = fmaxf(fmaf(-2.0f, cp, ic[k].x + ppn), 0.0f);
            const float num = 2.0f * (cp - ppn);
            const float denom = fmaf(denom_base, fsqrt_approx(dd), EPS);
            float cosang = __fdividef(num, denom);
            cosang = fminf(fmaxf(cosang, -1.0f + EPS), 1.0f - EPS);
            // exact self-pair semantics: reference gets num=0, denom=EPS -> cosang=0
            cosang = (cidx[k] == pr.x) ? 0.0f : cosang;
            const float ang = acos_approx(cosang);
            const float e   = fmaxf(ang - aperture, 0.0f);
            if (k == 0) pos_sum += e;
            else        neg_sum += fmaxf(MARGIN - e, 0.0f);
        }
    }

    // per-block reduction (pos/neg are warp-uniform)
    __shared__ float2 s[NTHREADS / 32];
    __shared__ bool   s_last;
    if (lane == 0)
        s[threadIdx.x >> 5] = make_float2(pos_sum, neg_sum);
    __syncthreads();
    if (threadIdx.x == 0) {
        float2 acc = s[0];
#pragma unroll
        for (int w = 1; w < NTHREADS / 32; w++) {
            acc.x += s[w].x;
            acc.y += s[w].y;
        }
        g_partials[blockIdx.x] = acc;
        __threadfence();
        unsigned int t = atomicAdd(&g_count, 1u);
        s_last = (t == (unsigned int)(NBLOCKS - 1));
    }
    __syncthreads();

    if (s_last) {
        __shared__ float sx[NTHREADS];
        __shared__ float sy[NTHREADS];
        float ax = 0.0f, ay = 0.0f;
        for (int b = threadIdx.x; b < NBLOCKS; b += NTHREADS) {
            float2 v = g_partials[b];
            ax += v.x;
            ay += v.y;
        }
        sx[threadIdx.x] = ax;
        sy[threadIdx.x] = ay;
        __syncthreads();
#pragma unroll
        for (int st = NTHREADS / 2; st > 0; st >>= 1) {
            if (threadIdx.x < st) {
                sx[threadIdx.x] += sx[threadIdx.x + st];
                sy[threadIdx.x] += sy[threadIdx.x + st];
            }
            __syncthreads();
        }
        if (threadIdx.x == 0) {
            const float avg_pos = sx[0] / (float)P_PAIRS;
            const float avg_neg = sy[0] / (float)(P_PAIRS * K_NEG);
            out[0] = (avg_pos + avg_neg) * 0.5f;
            g_count = 0;   // reset for next graph replay
        }
    }
}

extern "C" void kernel_launch(void* const* d_in, const int* in_sizes, int n_in,
                              void* d_out, int out_size)
{
    (void)in_sizes; (void)n_in; (void)out_size;
    const float* proto = (const float*)d_in[0];
    const int*   pairs = (const int*)d_in[1];
    const int*   negc  = (const int*)d_in[2];
    float* out = (float*)d_out;

    quant_kernel<<<QNT_BLOCKS, 256>>>(proto);
    energy_kernel<<<NBLOCKS, NTHREADS>>>(pairs, negc, out);
}